// round 2
// baseline (speedup 1.0000x reference)
#include <cuda_runtime.h>
#include <mma.h>

using namespace nvcuda;

#define DIM   768
#define NOUT  2304          // 3*DIM
#define RANK  16

// Folded effective weight: Weff[o][d] = Wqkv[o][d] + B_s[o'][r]*A_s[r][d]
__device__ float g_Weff[NOUT * DIM];

__global__ void fold_weights_kernel(const float* __restrict__ W,
                                    const float* __restrict__ Aq, const float* __restrict__ Bq,
                                    const float* __restrict__ Ak, const float* __restrict__ Bk,
                                    const float* __restrict__ Av, const float* __restrict__ Bv) {
    int idx = blockIdx.x * 256 + threadIdx.x;
    if (idx >= NOUT * DIM) return;
    int o = idx / DIM;
    int d = idx - o * DIM;
    int s = o / DIM;          // 0=q, 1=k, 2=v
    int op = o - s * DIM;     // row within slice
    const float* A = (s == 0) ? Aq : (s == 1) ? Ak : Av;   // [RANK, DIM]
    const float* B = (s == 0) ? Bq : (s == 1) ? Bk : Bv;   // [DIM, RANK]
    float acc = W[idx];
#pragma unroll
    for (int r = 0; r < RANK; r++) {
        acc += B[op * RANK + r] * A[r * DIM + d];
    }
    g_Weff[idx] = acc;
}

// GEMM: out[m][n] = sum_k x[m][k] * Weff[n][k] + bias[n]
// Block tile 128x64, BK=32, 8 warps (4x2), warp tile 32x32 (2x2 wmma 16x16x8 tf32)
#define BM 128
#define BN 64
#define BK 32
#define LDA 40   // BK + 8 pad (floats)
#define LDB 40

__global__ __launch_bounds__(256) void lora_qkv_gemm_kernel(
    const float* __restrict__ x,
    const float* __restrict__ bias,
    float* __restrict__ out,
    int M) {

    __shared__ float smem[8192];         // 32KB: A(5120)+B(2560) then reused as C(8192)
    __shared__ float bb[BN];
    float* As = smem;                     // [BM][LDA]
    float* Bs = smem + BM * LDA;          // [BN][LDB]

    const int tid = threadIdx.x;
    const int warp_id = tid >> 5;
    const int wm = warp_id & 3;           // 0..3  -> M offset wm*32
    const int wn = warp_id >> 2;          // 0..1  -> N offset wn*32

    const int gm0 = blockIdx.y * BM;
    const int gn0 = blockIdx.x * BN;

    if (tid < BN) bb[tid] = bias[gn0 + tid];

    wmma::fragment<wmma::accumulator, 16, 16, 8, float> acc[2][2];
#pragma unroll
    for (int i = 0; i < 2; i++)
#pragma unroll
        for (int j = 0; j < 2; j++)
            wmma::fill_fragment(acc[i][j], 0.0f);

    const float* xg = x + (size_t)gm0 * DIM;
    const float* wg = g_Weff + (size_t)gn0 * DIM;

    for (int k0 = 0; k0 < DIM; k0 += BK) {
        // Load A tile: 128 rows x 32 cols = 1024 float4, 4 per thread
#pragma unroll
        for (int i = 0; i < 4; i++) {
            int f4 = tid + i * 256;
            int row = f4 >> 3;            // /8 (8 float4 per row)
            int c4  = f4 & 7;
            float4 v = *reinterpret_cast<const float4*>(xg + (size_t)row * DIM + k0 + c4 * 4);
            *reinterpret_cast<float4*>(As + row * LDA + c4 * 4) = v;
        }
        // Load B tile: 64 rows x 32 cols = 512 float4, 2 per thread
#pragma unroll
        for (int i = 0; i < 2; i++) {
            int f4 = tid + i * 256;
            int row = f4 >> 3;
            int c4  = f4 & 7;
            float4 v = *reinterpret_cast<const float4*>(wg + (size_t)row * DIM + k0 + c4 * 4);
            *reinterpret_cast<float4*>(Bs + row * LDB + c4 * 4) = v;
        }
        __syncthreads();

#pragma unroll
        for (int kk = 0; kk < BK; kk += 8) {
            wmma::fragment<wmma::matrix_a, 16, 16, 8, wmma::precision::tf32, wmma::row_major> a[2];
            wmma::fragment<wmma::matrix_b, 16, 16, 8, wmma::precision::tf32, wmma::col_major> b[2];
#pragma unroll
            for (int i = 0; i < 2; i++) {
                wmma::load_matrix_sync(a[i], As + (wm * 32 + i * 16) * LDA + kk, LDA);
#pragma unroll
                for (int t = 0; t < a[i].num_elements; t++)
                    a[i].x[t] = wmma::__float_to_tf32(a[i].x[t]);
            }
#pragma unroll
            for (int j = 0; j < 2; j++) {
                wmma::load_matrix_sync(b[j], Bs + (wn * 32 + j * 16) * LDB + kk, LDB);
#pragma unroll
                for (int t = 0; t < b[j].num_elements; t++)
                    b[j].x[t] = wmma::__float_to_tf32(b[j].x[t]);
            }
#pragma unroll
            for (int i = 0; i < 2; i++)
#pragma unroll
                for (int j = 0; j < 2; j++)
                    wmma::mma_sync(acc[i][j], a[i], b[j], acc[i][j]);
        }
        __syncthreads();
    }

    // Epilogue: stage C in shared, add bias, write coalesced
    float* Cs = smem;                     // [BM][BN]
#pragma unroll
    for (int i = 0; i < 2; i++)
#pragma unroll
        for (int j = 0; j < 2; j++)
            wmma::store_matrix_sync(Cs + (wm * 32 + i * 16) * BN + wn * 32 + j * 16,
                                    acc[i][j], BN, wmma::mem_row_major);
    __syncthreads();

    float* og = out + (size_t)gm0 * NOUT + gn0;
#pragma unroll
    for (int i = 0; i < 32; i++) {
        int e = tid + i * 256;            // 0..8191
        int row = e >> 6;                 // /64
        int col = e & 63;
        og[(size_t)row * NOUT + col] = Cs[row * BN + col] + bb[col];
    }
}

extern "C" void kernel_launch(void* const* d_in, const int* in_sizes, int n_in,
                              void* d_out, int out_size) {
    const float* x    = (const float*)d_in[0];
    const float* Wqkv = (const float*)d_in[1];
    const float* bqkv = (const float*)d_in[2];
    const float* Aq   = (const float*)d_in[3];
    const float* Bq   = (const float*)d_in[4];
    const float* Ak   = (const float*)d_in[5];
    const float* Bk   = (const float*)d_in[6];
    const float* Av   = (const float*)d_in[7];
    const float* Bv   = (const float*)d_in[8];
    float* out = (float*)d_out;

    int M = in_sizes[0] / DIM;            // 32768 tokens

    // 1) Fold LoRA into effective weight
    int fold_elems = NOUT * DIM;
    fold_weights_kernel<<<(fold_elems + 255) / 256, 256>>>(Wqkv, Aq, Bq, Ak, Bk, Av, Bv);

    // 2) Single fused GEMM + bias
    dim3 grid(NOUT / BN, M / BM);         // 36 x 256
    lora_qkv_gemm_kernel<<<grid, 256>>>(x, bqkv, out, M);
}

// round 4
// speedup vs baseline: 4.5505x; 4.5505x over previous
#include <cuda_runtime.h>
#include <cuda_fp16.h>
#include <cstdint>
#include <cstddef>

#define DIM   768
#define NOUT  2304
#define RANK  16
#define MTOT  32768
#define BM    128
#define BN    128
#define BK    64
#define KT    12          // 768/64
#define NSTG  3
#define STG_A 16384       // 128 rows * 128B
#define STGB  32768
#define SMEM_TOTAL (512 + NSTG * STGB)   // 98816

__device__ __align__(1024) __half g_wh[NOUT * DIM];
__device__ __align__(1024) __half g_xh[MTOT * DIM];

__device__ __forceinline__ uint32_t smem_u32(const void* p) {
    uint32_t a;
    asm("{ .reg .u64 t; cvta.to.shared.u64 t, %1; cvt.u32.u64 %0, t; }" : "=r"(a) : "l"(p));
    return a;
}
#define CP16(dst, src) \
    asm volatile("cp.async.cg.shared.global [%0], [%1], 16;" :: "r"(dst), "l"(src))
#define CP_COMMIT() asm volatile("cp.async.commit_group;" ::: "memory")
#define CP_WAIT1()  asm volatile("cp.async.wait_group 1;" ::: "memory")
#define LDSM_X4(r0, r1, r2, r3, addr) \
    asm volatile("ldmatrix.sync.aligned.m8n8.x4.shared.b16 {%0,%1,%2,%3}, [%4];" \
        : "=r"(r0), "=r"(r1), "=r"(r2), "=r"(r3) : "r"(addr))
#define MMA16816(c, a, b0v, b1v) \
    asm volatile("mma.sync.aligned.m16n8k16.row.col.f32.f16.f16.f32 " \
        "{%0,%1,%2,%3}, {%4,%5,%6,%7}, {%8,%9}, {%0,%1,%2,%3};" \
        : "+f"((c)[0]), "+f"((c)[1]), "+f"((c)[2]), "+f"((c)[3]) \
        : "r"((a)[0]), "r"((a)[1]), "r"((a)[2]), "r"((a)[3]), "r"(b0v), "r"(b1v))

__global__ void conv_x_kernel(const float* __restrict__ x, int n8) {
    int i = blockIdx.x * 256 + threadIdx.x;
    if (i >= n8) return;
    float4 v0 = reinterpret_cast<const float4*>(x)[i * 2];
    float4 v1 = reinterpret_cast<const float4*>(x)[i * 2 + 1];
    __half2 h[4];
    h[0] = __float22half2_rn(make_float2(v0.x, v0.y));
    h[1] = __float22half2_rn(make_float2(v0.z, v0.w));
    h[2] = __float22half2_rn(make_float2(v1.x, v1.y));
    h[3] = __float22half2_rn(make_float2(v1.z, v1.w));
    reinterpret_cast<uint4*>(g_xh)[i] = *reinterpret_cast<uint4*>(h);
}

__global__ void fold_weights_kernel(const float* __restrict__ W,
                                    const float* __restrict__ Aq, const float* __restrict__ Bq,
                                    const float* __restrict__ Ak, const float* __restrict__ Bk,
                                    const float* __restrict__ Av, const float* __restrict__ Bv) {
    int idx = blockIdx.x * 256 + threadIdx.x;
    if (idx >= NOUT * DIM) return;
    int o = idx / DIM;
    int d = idx - o * DIM;
    int s = o / DIM;
    int op = o - s * DIM;
    const float* A = (s == 0) ? Aq : (s == 1) ? Ak : Av;
    const float* B = (s == 0) ? Bq : (s == 1) ? Bk : Bv;
    float acc = W[idx];
#pragma unroll
    for (int r = 0; r < RANK; r++) acc += B[op * RANK + r] * A[r * DIM + d];
    g_wh[idx] = __float2half_rn(acc);
}

// out[m][n] = sum_k xh[m][k] * wh[n][k] + bias[n]
__global__ __launch_bounds__(256, 2) void gemm_f16(const float* __restrict__ bias,
                                                   float* __restrict__ out) {
    extern __shared__ __align__(1024) char smem[];
    float* bsm = reinterpret_cast<float*>(smem);
    const uint32_t sbase = smem_u32(smem + 512);

    const int tid = threadIdx.x;
    const int lane = tid & 31;
    const int wid = tid >> 5;
    const int wm = wid & 3;          // warp M index (0..3) -> rows wm*32
    const int wn = wid >> 2;         // warp N index (0..1) -> cols wn*64
    const int gm0 = blockIdx.y * BM;
    const int gn0 = blockIdx.x * BN;

    if (tid < 128) bsm[tid] = bias[gn0 + tid];

    const __half* gA = g_xh + (size_t)gm0 * DIM;
    const __half* gB = g_wh + (size_t)gn0 * DIM;

    // per-thread cp.async coords (8 chunks of 16B per 128x64 tile per thread: 4 each A/B)
    const int ldr = tid >> 3;            // row for chunk 0 (0..31), +32 per i
    const int ldc = tid & 7;             // 16B chunk within 128B row

    float acc[2][8][4];
#pragma unroll
    for (int i = 0; i < 2; i++)
#pragma unroll
        for (int n = 0; n < 8; n++)
#pragma unroll
            for (int t = 0; t < 4; t++) acc[i][n][t] = 0.0f;

#pragma unroll
    for (int p = 0; p < NSTG - 1; p++) {
        uint32_t st = sbase + p * STGB;
        const __half* a = gA + p * BK;
        const __half* b = gB + p * BK;
#pragma unroll
        for (int i = 0; i < 4; i++) {
            int r = ldr + i * 32;
            uint32_t off = (uint32_t)(r * 128) + (uint32_t)(((ldc ^ (r & 7)) << 4));
            CP16(st + off, a + (size_t)r * DIM + ldc * 8);
            CP16(st + STG_A + off, b + (size_t)r * DIM + ldc * 8);
        }
        CP_COMMIT();
    }

    for (int kt = 0; kt < KT; kt++) {
        CP_WAIT1();
        __syncthreads();

        // prefetch stage kt+2
        int nk = kt + NSTG - 1;
        if (nk < KT) {
            uint32_t st = sbase + (nk % NSTG) * STGB;
            const __half* a = gA + nk * BK;
            const __half* b = gB + nk * BK;
#pragma unroll
            for (int i = 0; i < 4; i++) {
                int r = ldr + i * 32;
                uint32_t off = (uint32_t)(r * 128) + (uint32_t)(((ldc ^ (r & 7)) << 4));
                CP16(st + off, a + (size_t)r * DIM + ldc * 8);
                CP16(st + STG_A + off, b + (size_t)r * DIM + ldc * 8);
            }
        }
        CP_COMMIT();

        const uint32_t stA = sbase + (kt % NSTG) * STGB;
        const uint32_t stB = stA + STG_A;
        const int rowA = wm * 32 + (lane & 15);
        const int rowB = wn * 64 + (lane & 15);

#pragma unroll
        for (int kk = 0; kk < 4; kk++) {
            const int cb = kk * 2 + (lane >> 4);
            uint32_t af[2][4];
            uint32_t aaddr = stA + (uint32_t)(rowA * 128) + (uint32_t)(((cb ^ (rowA & 7)) << 4));
            LDSM_X4(af[0][0], af[0][1], af[0][2], af[0][3], aaddr);
            LDSM_X4(af[1][0], af[1][1], af[1][2], af[1][3], aaddr + 16 * 128);

            uint32_t bf[4][4];
            uint32_t baddr = stB + (uint32_t)(rowB * 128) + (uint32_t)(((cb ^ (rowB & 7)) << 4));
#pragma unroll
            for (int j = 0; j < 4; j++)
                LDSM_X4(bf[j][0], bf[j][1], bf[j][2], bf[j][3], baddr + j * 16 * 128);

#pragma unroll
            for (int i = 0; i < 2; i++)
#pragma unroll
                for (int n = 0; n < 8; n++) {
                    int j = n >> 1, h = n & 1;
                    MMA16816(acc[i][n], af[i], bf[j][h], bf[j][h + 2]);
                }
        }
        __syncthreads();
    }

    // Epilogue: direct float2 stores (32B sectors), bias from smem
    const int r0 = wm * 32 + (lane >> 2);
    const int c0 = wn * 64 + (lane & 3) * 2;
    float* ob = out + (size_t)gm0 * NOUT + gn0;
#pragma unroll
    for (int i = 0; i < 2; i++) {
#pragma unroll
        for (int n = 0; n < 8; n++) {
            int col = c0 + n * 8;
            float b0 = bsm[col], b1 = bsm[col + 1];
            int row = r0 + i * 16;
            float2 v0 = make_float2(acc[i][n][0] + b0, acc[i][n][1] + b1);
            float2 v1 = make_float2(acc[i][n][2] + b0, acc[i][n][3] + b1);
            *reinterpret_cast<float2*>(ob + (size_t)row * NOUT + col) = v0;
            *reinterpret_cast<float2*>(ob + (size_t)(row + 8) * NOUT + col) = v1;
        }
    }
}

extern "C" void kernel_launch(void* const* d_in, const int* in_sizes, int n_in,
                              void* d_out, int out_size) {
    const float* x    = (const float*)d_in[0];
    const float* Wqkv = (const float*)d_in[1];
    const float* bqkv = (const float*)d_in[2];
    const float* Aq   = (const float*)d_in[3];
    const float* Bq   = (const float*)d_in[4];
    const float* Ak   = (const float*)d_in[5];
    const float* Bk   = (const float*)d_in[6];
    const float* Av   = (const float*)d_in[7];
    const float* Bv   = (const float*)d_in[8];
    float* out = (float*)d_out;

    int M = in_sizes[0] / DIM;   // 32768
    cudaFuncSetAttribute(gemm_f16, cudaFuncAttributeMaxDynamicSharedMemorySize, SMEM_TOTAL);

    int n8 = M * DIM / 8;
    conv_x_kernel<<<(n8 + 255) / 256, 256>>>(x, n8);
    fold_weights_kernel<<<(NOUT * DIM + 255) / 256, 256>>>(Wqkv, Aq, Bq, Ak, Bk, Av, Bv);

    dim3 grid(NOUT / BN, M / BM);   // 18 x 256
    gemm_f16<<<grid, 256, SMEM_TOTAL>>>(bqkv, out);
}